// round 10
// baseline (speedup 1.0000x reference)
#include <cuda_runtime.h>
#include <math.h>

#define BATCH 64
#define T 128
#define NS 32
#define MD 8
#define PD 16
#define ST 36      // padded stride for 32-wide (144B rows -> float4 aligned)
#define SP 20      // padded stride for 16-wide (80B rows -> float4 aligned)
#define QVAR 0.01f
#define RVAR 0.01f

#define TBAR(id) asm volatile("bar.sync %0, %1;" :: "r"(id), "r"(256) : "memory")

// Scratch (forward-pass products consumed later).
__device__ __align__(16) float g_muf [BATCH * T * NS];
__device__ __align__(16) float g_mup [BATCH * T * NS];
__device__ __align__(16) float g_Sigf[BATCH * T * NS * NS];
__device__ __align__(16) float g_Sigp[BATCH * T * NS * NS];
__device__ __align__(16) float g_J   [BATCH * T * NS * NS];  // J transposed: [t][k][i] = J[i][k]

struct __align__(16) FwdS {
    float At [NS][ST];   // A^T (k-major)
    float Sig[NS][ST];   // carry Sigma_f (init Sigma0)
    float T1 [NS][ST];   // (A*Sig)^T
    float Sp [NS][ST];   // Sigma_pred
    float Ct [NS][SP];   // C^T (k-major)
    float W  [NS][SP];   // W = Sp C^T
    float Wt [PD][ST];   // W^T
    float Kt [PD][ST];   // K^T
    float S  [PD][SP];   // innovation cov (chol in place)
    float B  [NS][MD];
    float mu[NS], mup[NS], r[PD], y[PD], uu[MD];
    float pad[8];
};

struct __align__(16) BwdS {
    float Sig[NS][ST];   // smoothed carry
    float T1 [NS][ST];
    float Jt[2][NS][ST], Sf[2][NS][ST], Sp[2][NS][ST];
    float muP[2][NS], mufB[2][NS], mupB[2][NS];
    float pad[8];
};

// ============================ FORWARD FILTER (2 teams / CTA, 4x4 tiles) ============================
__global__ __launch_bounds__(512, 1)
void fwd_kernel(const float* __restrict__ Y, const float* __restrict__ U,
                const float* __restrict__ A, const float* __restrict__ Bm,
                const float* __restrict__ C, const float* __restrict__ mu0,
                const float* __restrict__ Sig0, float* __restrict__ out)
{
    extern __shared__ __align__(16) char dyn[];
    __shared__ unsigned char mR8[36], mC8[36], mR4[10], mC4[10];

    const int tid  = threadIdx.x;
    const int team = tid >> 8, rt = tid & 255;
    const int b    = blockIdx.x * 2 + team;
    const int bar  = 1 + team;
    FwdS& s = ((FwdS*)dyn)[team];
    const int mm = team ? (rt ^ 64) : rt;       // SMSP-disjoint role index

    if (tid == 0) {
        int e = 0;
        for (int r = 0; r < 8; ++r)
            for (int c = r; c < 8; ++c) { mR8[e] = (unsigned char)r; mC8[e] = (unsigned char)c; ++e; }
        e = 0;
        for (int r = 0; r < 4; ++r)
            for (int c = r; c < 4; ++c) { mR4[e] = (unsigned char)r; mC4[e] = (unsigned char)c; ++e; }
    }
    {
        const size_t o = (size_t)b * T;
        const float* A0 = A  + o * NS * NS;
        const float* C0 = C  + o * PD * NS;
        const float* B0 = Bm + o * NS * MD;
        for (int e = rt; e < NS * NS; e += 256) { s.At[e & 31][e >> 5] = A0[e]; s.Sig[e >> 5][e & 31] = Sig0[e]; }
        for (int e = rt; e < PD * NS; e += 256) s.Ct[e & 31][e >> 5] = C0[e];
        s.B[rt >> 3][rt & 7] = B0[rt];
        if (rt < PD) s.y[rt] = Y[o * PD + rt];
        else if (rt < PD + MD) s.uu[rt - PD] = U[o * MD + (rt - PD)];
        if (rt >= 32 && rt < 64) s.mu[rt - 32] = mu0[rt - 32];
    }
    __syncthreads();

    for (int t = 0; t < T; ++t) {
        const size_t bt = (size_t)b * T + t;

        // --- P1: T1^T = (A*Sig)^T (64 4x4 tiles) ; mu_p ---
        if (mm < 64) {
            const int i0 = 4 * (mm >> 3), j0 = 4 * (mm & 7);
            float c[4][4] = {};
            #pragma unroll 8
            for (int k = 0; k < NS; ++k) {
                float4 a  = *(const float4*)&s.At[k][i0];
                float4 bb = *(const float4*)&s.Sig[k][j0];
                c[0][0] += a.x * bb.x; c[0][1] += a.x * bb.y; c[0][2] += a.x * bb.z; c[0][3] += a.x * bb.w;
                c[1][0] += a.y * bb.x; c[1][1] += a.y * bb.y; c[1][2] += a.y * bb.z; c[1][3] += a.y * bb.w;
                c[2][0] += a.z * bb.x; c[2][1] += a.z * bb.y; c[2][2] += a.z * bb.z; c[2][3] += a.z * bb.w;
                c[3][0] += a.w * bb.x; c[3][1] += a.w * bb.y; c[3][2] += a.w * bb.z; c[3][3] += a.w * bb.w;
            }
            #pragma unroll
            for (int m = 0; m < 4; ++m)
                #pragma unroll
                for (int n = 0; n < 4; ++n) s.T1[j0 + n][i0 + m] = c[m][n];
        } else if (mm < 96) {
            const int i = mm - 64;
            float acc = 0.f;
            #pragma unroll 8
            for (int k = 0; k < NS; ++k) acc += s.At[k][i] * s.mu[k];
            #pragma unroll
            for (int k = 0; k < MD; ++k) acc += s.B[i][k] * s.uu[k];
            s.mup[i] = acc;
        }
        TBAR(bar);

        // --- P2: Sp = sym(T1 A^T)+Q (36 upper 4x4 tiles) ; r ; g_mup ---
        if (mm < 36) {
            const int ti = mR8[mm], tj = mC8[mm];
            const int i0 = 4 * ti, j0 = 4 * tj;
            float c[4][4] = {};
            #pragma unroll 8
            for (int k = 0; k < NS; ++k) {
                float4 a  = *(const float4*)&s.T1[k][i0];
                float4 bb = *(const float4*)&s.At[k][j0];
                c[0][0] += a.x * bb.x; c[0][1] += a.x * bb.y; c[0][2] += a.x * bb.z; c[0][3] += a.x * bb.w;
                c[1][0] += a.y * bb.x; c[1][1] += a.y * bb.y; c[1][2] += a.y * bb.z; c[1][3] += a.y * bb.w;
                c[2][0] += a.z * bb.x; c[2][1] += a.z * bb.y; c[2][2] += a.z * bb.z; c[2][3] += a.z * bb.w;
                c[3][0] += a.w * bb.x; c[3][1] += a.w * bb.y; c[3][2] += a.w * bb.z; c[3][3] += a.w * bb.w;
            }
            if (ti == tj) {
                #pragma unroll
                for (int m = 0; m < 4; ++m) {
                    c[m][m] += QVAR;
                    #pragma unroll
                    for (int n = m + 1; n < 4; ++n) { float av = 0.5f * (c[m][n] + c[n][m]); c[m][n] = av; c[n][m] = av; }
                }
                #pragma unroll
                for (int m = 0; m < 4; ++m)
                    #pragma unroll
                    for (int n = 0; n < 4; ++n) s.Sp[i0 + m][j0 + n] = c[m][n];
            } else {
                #pragma unroll
                for (int m = 0; m < 4; ++m)
                    #pragma unroll
                    for (int n = 0; n < 4; ++n) { s.Sp[i0 + m][j0 + n] = c[m][n]; s.Sp[j0 + n][i0 + m] = c[m][n]; }
            }
        } else if (mm >= 96 && mm < 112) {
            const int i = mm - 96;
            float acc = s.y[i];
            #pragma unroll 8
            for (int k = 0; k < NS; ++k) acc -= s.Ct[k][i] * s.mup[k];
            s.r[i] = acc;
        } else if (mm >= 128 && mm < 160) {
            g_mup[bt * NS + (mm - 128)] = s.mup[mm - 128];
        }
        TBAR(bar);

        // --- P3: W = Sp C^T (32 4x4 tiles, both layouts) ; g_Sigp store ---
        if (mm < 32) {
            const int i0 = 4 * (mm >> 2), j0 = 4 * (mm & 3);
            float c[4][4] = {};
            #pragma unroll 8
            for (int k = 0; k < NS; ++k) {
                float4 a  = *(const float4*)&s.Sp[k][i0];
                float4 bb = *(const float4*)&s.Ct[k][j0];
                c[0][0] += a.x * bb.x; c[0][1] += a.x * bb.y; c[0][2] += a.x * bb.z; c[0][3] += a.x * bb.w;
                c[1][0] += a.y * bb.x; c[1][1] += a.y * bb.y; c[1][2] += a.y * bb.z; c[1][3] += a.y * bb.w;
                c[2][0] += a.z * bb.x; c[2][1] += a.z * bb.y; c[2][2] += a.z * bb.z; c[2][3] += a.z * bb.w;
                c[3][0] += a.w * bb.x; c[3][1] += a.w * bb.y; c[3][2] += a.w * bb.z; c[3][3] += a.w * bb.w;
            }
            #pragma unroll
            for (int m = 0; m < 4; ++m)
                #pragma unroll
                for (int n = 0; n < 4; ++n) { s.W[i0 + m][j0 + n] = c[m][n]; s.Wt[j0 + n][i0 + m] = c[m][n]; }
        } else if (mm >= 128) {
            float* gp = g_Sigp + bt * NS * NS;
            for (int e = mm - 128; e < NS * NS; e += 128) gp[e] = s.Sp[e >> 5][e & 31];
        }
        TBAR(bar);

        // --- P4: S = sym(C W)+R (10 upper 4x4 tiles) ---
        if (mm < 10) {
            const int ti = mR4[mm], tj = mC4[mm];
            const int i0 = 4 * ti, j0 = 4 * tj;
            float c[4][4] = {};
            #pragma unroll 8
            for (int k = 0; k < NS; ++k) {
                float4 a  = *(const float4*)&s.Ct[k][i0];
                float4 bb = *(const float4*)&s.W[k][j0];
                c[0][0] += a.x * bb.x; c[0][1] += a.x * bb.y; c[0][2] += a.x * bb.z; c[0][3] += a.x * bb.w;
                c[1][0] += a.y * bb.x; c[1][1] += a.y * bb.y; c[1][2] += a.y * bb.z; c[1][3] += a.y * bb.w;
                c[2][0] += a.z * bb.x; c[2][1] += a.z * bb.y; c[2][2] += a.z * bb.z; c[2][3] += a.z * bb.w;
                c[3][0] += a.w * bb.x; c[3][1] += a.w * bb.y; c[3][2] += a.w * bb.z; c[3][3] += a.w * bb.w;
            }
            if (ti == tj) {
                #pragma unroll
                for (int m = 0; m < 4; ++m) {
                    c[m][m] += RVAR;
                    #pragma unroll
                    for (int n = m + 1; n < 4; ++n) { float av = 0.5f * (c[m][n] + c[n][m]); c[m][n] = av; c[n][m] = av; }
                }
                #pragma unroll
                for (int m = 0; m < 4; ++m)
                    #pragma unroll
                    for (int n = 0; n < 4; ++n) s.S[i0 + m][j0 + n] = c[m][n];
            } else {
                #pragma unroll
                for (int m = 0; m < 4; ++m)
                    #pragma unroll
                    for (int n = 0; n < 4; ++n) { s.S[i0 + m][j0 + n] = c[m][n]; s.S[j0 + n][i0 + m] = c[m][n]; }
            }
        }
        TBAR(bar);

        // --- P5: chol16+solve -> Kt (warp mm<32) ; others prefetch t+1 ---
        if (mm < 32) {
            const int i = rt & 31;   // lane id within the chol warp
            float dinv[PD];
            #pragma unroll
            for (int k = 0; k < PD; ++k) {
                float dkk = s.S[k][k];
                float rs  = rsqrtf(dkk);
                dinv[k] = rs;
                __syncwarp();
                if (i == k) s.S[k][k] = dkk * rs;
                if (i > k && i < PD) s.S[i][k] *= rs;
                __syncwarp();
                if (i > k && i < PD) {
                    float lik = s.S[i][k];
                    for (int j2 = k + 1; j2 <= i; ++j2) s.S[i][j2] -= lik * s.S[j2][k];
                }
                __syncwarp();
            }
            {
                float x[PD];
                #pragma unroll
                for (int r2 = 0; r2 < PD; ++r2) {
                    float a0 = s.W[i][r2], a1 = 0.f;
                    #pragma unroll
                    for (int k = 0; k < r2; ++k) {
                        if (k & 1) a1 += s.S[r2][k] * x[k];
                        else       a0 -= s.S[r2][k] * x[k];
                    }
                    x[r2] = (a0 - a1) * dinv[r2];
                }
                #pragma unroll
                for (int r2 = PD - 1; r2 >= 0; --r2) {
                    float a0 = x[r2], a1 = 0.f;
                    #pragma unroll
                    for (int k = r2 + 1; k < PD; ++k) {
                        if (k & 1) a1 += s.S[k][r2] * x[k];
                        else       a0 -= s.S[k][r2] * x[k];
                    }
                    x[r2] = (a0 - a1) * dinv[r2];
                }
                #pragma unroll
                for (int r2 = 0; r2 < PD; ++r2) s.Kt[r2][i] = x[r2];
            }
        } else if (t + 1 < T) {
            const size_t bt1 = bt + 1;
            const float* An = A  + bt1 * NS * NS;
            const float* Cn = C  + bt1 * PD * NS;
            const float* Bn = Bm + bt1 * NS * MD;
            const int q = mm - 32;
            for (int e = q; e < NS * NS; e += 224) s.At[e & 31][e >> 5] = An[e];
            for (int e = q; e < PD * NS; e += 224) s.Ct[e & 31][e >> 5] = Cn[e];
            for (int e = q; e < NS * MD; e += 224) s.B[e >> 3][e & 7] = Bn[e];
            if (q < PD) s.y[q] = Y[bt1 * PD + q];
            else if (q < PD + MD) s.uu[q - PD] = U[bt1 * MD + (q - PD)];
        }
        TBAR(bar);

        // --- P6: Sigf = sym(Sp - K W^T) (36 upper 4x4 tiles, PD-deep) ; mu_f ---
        {
            float* gf = g_Sigf + bt * NS * NS;
            float* ob = out + bt * (size_t)(NS * (NS + 1));
            if (mm < 36) {
                const int ti = mR8[mm], tj = mC8[mm];
                const int i0 = 4 * ti, j0 = 4 * tj;
                float c[4][4];
                #pragma unroll
                for (int m = 0; m < 4; ++m) {
                    float4 sp = *(const float4*)&s.Sp[i0 + m][j0];
                    c[m][0] = sp.x; c[m][1] = sp.y; c[m][2] = sp.z; c[m][3] = sp.w;
                }
                #pragma unroll
                for (int k = 0; k < PD; ++k) {
                    float4 a  = *(const float4*)&s.Kt[k][i0];
                    float4 bb = *(const float4*)&s.Wt[k][j0];
                    c[0][0] -= a.x * bb.x; c[0][1] -= a.x * bb.y; c[0][2] -= a.x * bb.z; c[0][3] -= a.x * bb.w;
                    c[1][0] -= a.y * bb.x; c[1][1] -= a.y * bb.y; c[1][2] -= a.y * bb.z; c[1][3] -= a.y * bb.w;
                    c[2][0] -= a.z * bb.x; c[2][1] -= a.z * bb.y; c[2][2] -= a.z * bb.z; c[2][3] -= a.z * bb.w;
                    c[3][0] -= a.w * bb.x; c[3][1] -= a.w * bb.y; c[3][2] -= a.w * bb.z; c[3][3] -= a.w * bb.w;
                }
                if (ti == tj) {
                    #pragma unroll
                    for (int m = 0; m < 4; ++m)
                        #pragma unroll
                        for (int n = m + 1; n < 4; ++n) { float av = 0.5f * (c[m][n] + c[n][m]); c[m][n] = av; c[n][m] = av; }
                    #pragma unroll
                    for (int m = 0; m < 4; ++m)
                        #pragma unroll
                        for (int n = 0; n < 4; ++n) {
                            s.Sig[i0 + m][j0 + n] = c[m][n];
                            gf[(i0 + m) * NS + j0 + n] = c[m][n];
                            if (t == T - 1) ob[(i0 + m) * (NS + 1) + 1 + j0 + n] = c[m][n];
                        }
                } else {
                    #pragma unroll
                    for (int m = 0; m < 4; ++m)
                        #pragma unroll
                        for (int n = 0; n < 4; ++n) {
                            s.Sig[i0 + m][j0 + n] = c[m][n]; s.Sig[j0 + n][i0 + m] = c[m][n];
                            gf[(i0 + m) * NS + j0 + n] = c[m][n]; gf[(j0 + n) * NS + i0 + m] = c[m][n];
                            if (t == T - 1) {
                                ob[(i0 + m) * (NS + 1) + 1 + j0 + n] = c[m][n];
                                ob[(j0 + n) * (NS + 1) + 1 + i0 + m] = c[m][n];
                            }
                        }
                }
            } else if (mm >= 64 && mm < 96) {
                const int i = mm - 64;
                float acc = s.mup[i];
                #pragma unroll
                for (int k = 0; k < PD; ++k) acc += s.Kt[k][i] * s.r[k];
                s.mu[i] = acc;
                g_muf[bt * NS + i] = acc;
                if (t == T - 1) ob[i * (NS + 1)] = acc;
            }
        }
        TBAR(bar);
    }
}

// ============================ J PRECOMPUTE (fully parallel) ============================
__global__ __launch_bounds__(32, 1)
void jpre_kernel(const float* __restrict__ A)
{
    __shared__ __align__(16) float sl[NS][33];
    const int lane = threadIdx.x;
    const int b = blockIdx.x;
    const int t = blockIdx.y;
    const size_t bt = (size_t)b * T + t;
    const float* Ag  = A      + bt * NS * NS;
    const float* Sfg = g_Sigf + bt * NS * NS;
    const float* Spg = g_Sigp + (bt + 1) * NS * NS;

    #pragma unroll
    for (int e = lane; e < NS * NS / 4; e += 32) {
        float4 v = ((const float4*)Ag)[e];
        int r = (4 * e) >> 5, c = (4 * e) & 31;
        sl[r][c] = v.x; sl[r][c + 1] = v.y; sl[r][c + 2] = v.z; sl[r][c + 3] = v.w;
    }
    float sf[NS];
    #pragma unroll
    for (int q = 0; q < 8; ++q) {
        float4 v = ((const float4*)(Sfg + lane * NS))[q];
        sf[4 * q] = v.x; sf[4 * q + 1] = v.y; sf[4 * q + 2] = v.z; sf[4 * q + 3] = v.w;
    }
    __syncwarp();
    float m[NS];
    #pragma unroll
    for (int r = 0; r < NS; ++r) {
        float a0 = 0.f, a1 = 0.f;
        #pragma unroll 8
        for (int k = 0; k < NS; k += 2) { a0 += sf[k] * sl[r][k]; a1 += sf[k + 1] * sl[r][k + 1]; }
        m[r] = a0 + a1;
    }
    __syncwarp();
    #pragma unroll
    for (int e = lane; e < NS * NS / 4; e += 32) {
        float4 v = ((const float4*)Spg)[e];
        int r = (4 * e) >> 5, c = (4 * e) & 31;
        sl[r][c] = v.x; sl[r][c + 1] = v.y; sl[r][c + 2] = v.z; sl[r][c + 3] = v.w;
    }
    __syncwarp();
    {
        const int i = lane;
        #pragma unroll 1
        for (int k = 0; k < NS; ++k) {
            float dkk = sl[k][k];
            float rs  = rsqrtf(dkk);
            __syncwarp();
            if (i == k) { sl[k][k] = dkk * rs; sl[k][32] = rs; }
            if (i > k) sl[i][k] *= rs;
            __syncwarp();
            if (i > k) {
                float lik = sl[i][k];
                for (int j2 = k + 1; j2 <= i; ++j2) sl[i][j2] -= lik * sl[j2][k];
            }
            __syncwarp();
        }
    }
    float x[NS];
    #pragma unroll
    for (int r = 0; r < NS; ++r) {
        float a0 = m[r], a1 = 0.f;
        #pragma unroll
        for (int k = 0; k < r; ++k) {
            if (k & 1) a1 += sl[r][k] * x[k];
            else       a0 -= sl[r][k] * x[k];
        }
        x[r] = (a0 - a1) * sl[r][32];
    }
    #pragma unroll
    for (int r = NS - 1; r >= 0; --r) {
        float a0 = x[r], a1 = 0.f;
        #pragma unroll
        for (int k = r + 1; k < NS; ++k) {
            if (k & 1) a1 += sl[k][r] * x[k];
            else       a0 -= sl[k][r] * x[k];
        }
        x[r] = (a0 - a1) * sl[r][32];
    }
    float* Jg = g_J + bt * NS * NS;
    #pragma unroll
    for (int k = 0; k < NS; ++k) Jg[k * NS + lane] = x[k];
}

// ============================ BACKWARD SMOOTHER (2 teams / CTA, 4x4 tiles) ============================
__global__ __launch_bounds__(512, 1)
void bwd_kernel(float* __restrict__ out)
{
    extern __shared__ __align__(16) char dyn[];
    __shared__ unsigned char mR8[36], mC8[36];

    const int tid  = threadIdx.x;
    const int team = tid >> 8, rt = tid & 255;
    const int b    = blockIdx.x * 2 + team;
    const int bar  = 1 + team;
    BwdS& s = ((BwdS*)dyn)[team];
    const int mm = team ? (rt ^ 64) : rt;

    if (tid == 0) {
        int e = 0;
        for (int r = 0; r < 8; ++r)
            for (int c = r; c < 8; ++c) { mR8[e] = (unsigned char)r; mC8[e] = (unsigned char)c; ++e; }
    }
    {
        const int t0 = T - 2, p0 = t0 & 1;
        const size_t bt  = (size_t)b * T + t0;
        const size_t btL = (size_t)b * T + (T - 1);
        const float* Sfg = g_Sigf + bt * NS * NS;
        const float* Spg = g_Sigp + (bt + 1) * NS * NS;
        const float* Jg  = g_J    + bt * NS * NS;
        const float* SfL = g_Sigf + btL * NS * NS;
        for (int e = rt; e < NS * NS; e += 256) {
            s.Sf[p0][e >> 5][e & 31] = Sfg[e];
            s.Sp[p0][e >> 5][e & 31] = Spg[e];
            s.Jt[p0][e >> 5][e & 31] = Jg[e];
            s.Sig[e >> 5][e & 31]    = SfL[e];
        }
        if (rt < NS) { s.mufB[p0][rt] = g_muf[bt * NS + rt]; s.muP[(T - 1) & 1][rt] = g_muf[btL * NS + rt]; }
        else if (rt < 2 * NS) s.mupB[p0][rt - NS] = g_mup[(bt + 1) * NS + (rt - NS)];
    }
    __syncthreads();

    for (int t = T - 2; t >= 0; --t) {
        const size_t bt = (size_t)b * T + t;
        const int p = t & 1;
        float (*Jt)[ST] = s.Jt[p];
        float (*Sf)[ST] = s.Sf[p];
        float (*Sp)[ST] = s.Sp[p];
        float* ob = out + bt * (size_t)(NS * (NS + 1));

        // phaseA: T1^T = (J (Sig_s - Sp))^T  (64 4x4 tiles)
        if (mm < 64) {
            const int i0 = 4 * (mm >> 3), j0 = 4 * (mm & 7);
            float c[4][4] = {};
            #pragma unroll 8
            for (int k = 0; k < NS; ++k) {
                float4 a  = *(const float4*)&Jt[k][i0];
                float4 s1 = *(const float4*)&s.Sig[k][j0];
                float4 s2 = *(const float4*)&Sp[k][j0];
                float bx = s1.x - s2.x, by = s1.y - s2.y, bz = s1.z - s2.z, bw = s1.w - s2.w;
                c[0][0] += a.x * bx; c[0][1] += a.x * by; c[0][2] += a.x * bz; c[0][3] += a.x * bw;
                c[1][0] += a.y * bx; c[1][1] += a.y * by; c[1][2] += a.y * bz; c[1][3] += a.y * bw;
                c[2][0] += a.z * bx; c[2][1] += a.z * by; c[2][2] += a.z * bz; c[2][3] += a.z * bw;
                c[3][0] += a.w * bx; c[3][1] += a.w * by; c[3][2] += a.w * bz; c[3][3] += a.w * bw;
            }
            #pragma unroll
            for (int m = 0; m < 4; ++m)
                #pragma unroll
                for (int n = 0; n < 4; ++n) s.T1[j0 + n][i0 + m] = c[m][n];
        }
        TBAR(bar);

        // phaseB: Sig_n = sym(Sf + T1 J^T) (36 tiles) ; mu_n ; prefetch t-1 (160 thr)
        if (mm < 36) {
            const int ti = mR8[mm], tj = mC8[mm];
            const int i0 = 4 * ti, j0 = 4 * tj;
            float c[4][4];
            #pragma unroll
            for (int m = 0; m < 4; ++m) {
                float4 sfv = *(const float4*)&Sf[i0 + m][j0];
                c[m][0] = sfv.x; c[m][1] = sfv.y; c[m][2] = sfv.z; c[m][3] = sfv.w;
            }
            #pragma unroll 8
            for (int k = 0; k < NS; ++k) {
                float4 a  = *(const float4*)&s.T1[k][i0];
                float4 bb = *(const float4*)&Jt[k][j0];
                c[0][0] += a.x * bb.x; c[0][1] += a.x * bb.y; c[0][2] += a.x * bb.z; c[0][3] += a.x * bb.w;
                c[1][0] += a.y * bb.x; c[1][1] += a.y * bb.y; c[1][2] += a.y * bb.z; c[1][3] += a.y * bb.w;
                c[2][0] += a.z * bb.x; c[2][1] += a.z * bb.y; c[2][2] += a.z * bb.z; c[2][3] += a.z * bb.w;
                c[3][0] += a.w * bb.x; c[3][1] += a.w * bb.y; c[3][2] += a.w * bb.z; c[3][3] += a.w * bb.w;
            }
            if (ti == tj) {
                #pragma unroll
                for (int m = 0; m < 4; ++m)
                    #pragma unroll
                    for (int n = m + 1; n < 4; ++n) { float av = 0.5f * (c[m][n] + c[n][m]); c[m][n] = av; c[n][m] = av; }
                #pragma unroll
                for (int m = 0; m < 4; ++m)
                    #pragma unroll
                    for (int n = 0; n < 4; ++n) {
                        s.Sig[i0 + m][j0 + n] = c[m][n];
                        ob[(i0 + m) * (NS + 1) + 1 + j0 + n] = c[m][n];
                    }
            } else {
                #pragma unroll
                for (int m = 0; m < 4; ++m)
                    #pragma unroll
                    for (int n = 0; n < 4; ++n) {
                        s.Sig[i0 + m][j0 + n] = c[m][n]; s.Sig[j0 + n][i0 + m] = c[m][n];
                        ob[(i0 + m) * (NS + 1) + 1 + j0 + n] = c[m][n];
                        ob[(j0 + n) * (NS + 1) + 1 + i0 + m] = c[m][n];
                    }
            }
        } else if (mm >= 64 && mm < 96) {
            const int i = mm - 64;
            float acc = s.mufB[p][i];
            #pragma unroll 8
            for (int k = 0; k < NS; ++k) acc += Jt[k][i] * (s.muP[p ^ 1][k] - s.mupB[p][k]);
            s.muP[p][i] = acc;
            ob[i * (NS + 1)] = acc;
        } else if (mm >= 96 && t > 0) {
            const int q = mm - 96;
            const size_t btm = bt - 1;
            const float* Sfg = g_Sigf + btm * NS * NS;
            const float* Spg = g_Sigp + bt * NS * NS;
            const float* Jg  = g_J    + btm * NS * NS;
            const int pn = p ^ 1;
            for (int e = q; e < NS * NS; e += 160) {
                s.Sf[pn][e >> 5][e & 31] = Sfg[e];
                s.Sp[pn][e >> 5][e & 31] = Spg[e];
                s.Jt[pn][e >> 5][e & 31] = Jg[e];
            }
            if (q < NS) s.mufB[pn][q] = g_muf[btm * NS + q];
            else if (q < 2 * NS) s.mupB[pn][q - NS] = g_mup[bt * NS + (q - NS)];
        }
        TBAR(bar);
    }
}

extern "C" void kernel_launch(void* const* d_in, const int* in_sizes, int n_in,
                              void* d_out, int out_size)
{
    const float* Y    = (const float*)d_in[0];
    const float* U    = (const float*)d_in[1];
    const float* A    = (const float*)d_in[2];
    const float* Bm   = (const float*)d_in[3];
    const float* C    = (const float*)d_in[4];
    const float* mu0  = (const float*)d_in[5];
    const float* Sig0 = (const float*)d_in[6];
    float* out = (float*)d_out;

    cudaFuncSetAttribute(fwd_kernel, cudaFuncAttributeMaxDynamicSharedMemorySize,
                         (int)(2 * sizeof(FwdS)));
    cudaFuncSetAttribute(bwd_kernel, cudaFuncAttributeMaxDynamicSharedMemorySize,
                         (int)(2 * sizeof(BwdS)));

    fwd_kernel<<<BATCH / 2, 512, 2 * sizeof(FwdS)>>>(Y, U, A, Bm, C, mu0, Sig0, out);
    jpre_kernel<<<dim3(BATCH, T - 1), 32>>>(A);
    bwd_kernel<<<BATCH / 2, 512, 2 * sizeof(BwdS)>>>(out);
}

// round 12
// speedup vs baseline: 1.0466x; 1.0466x over previous
#include <cuda_runtime.h>
#include <math.h>

#define BATCH 64
#define T 128
#define NS 32
#define MD 8
#define PD 16
#define ST 36      // stride for 32-wide rows (144B, float4-aligned)
#define SP 20      // stride for 16-wide rows (80B, float4-aligned)
#define QVAR 0.01f
#define RVAR 0.01f

#define TBAR(id) asm volatile("bar.sync %0, %1;" :: "r"(id), "r"(256) : "memory")

__device__ __align__(16) float g_muf [BATCH * T * NS];
__device__ __align__(16) float g_mup [BATCH * T * NS];
__device__ __align__(16) float g_Sigf[BATCH * T * NS * NS];
__device__ __align__(16) float g_Sigp[BATCH * T * NS * NS];
__device__ __align__(16) float g_J   [BATCH * T * NS * NS];  // J transposed: [t][k][i] = J[i][k]

struct __align__(16) FwdS {
    float At [NS][ST];   // A^T   (At[k][i] = A[i][k])
    float An [NS][ST];   // A natural
    float Sig[NS][ST];   // carry Sigma_f
    float T1t[NS][ST];   // T1 transposed (T1t[k][i] = T1[i][k])
    float T1n[NS][ST];   // T1 natural
    float Sp [NS][ST];   // Sigma_pred
    float Ct [NS][SP];   // C^T   (Ct[k][c] = C[c][k])
    float Gt [NS][SP];   // G=C*A transposed (Gt[k][c] = G[c][k])
    float Ht [NS][SP];   // H=C*T1 transposed
    float W  [NS][SP];   // W = Sp C^T
    float Wt [PD][ST];
    float Kt [PD][ST];
    float CC [PD][SP];   // C C^T
    float S  [PD][SP];
    float B  [NS][MD];
    float mu[NS], mup[NS], r[PD], y[PD], uu[MD];
    float pad[8];
};

struct __align__(16) BwdS {
    float Sig[NS][ST];
    float T1 [NS][ST];
    float Jt[2][NS][ST], Sf[2][NS][ST], Sp[2][NS][ST];
    float muP[2][NS], mufB[2][NS], mupB[2][NS];
    float pad[8];
};

// ============================ FORWARD FILTER (2 teams / CTA, 5 phases) ============================
__global__ __launch_bounds__(512, 1)
void fwd_kernel(const float* __restrict__ Y, const float* __restrict__ U,
                const float* __restrict__ A, const float* __restrict__ Bm,
                const float* __restrict__ C, const float* __restrict__ mu0,
                const float* __restrict__ Sig0, float* __restrict__ out)
{
    extern __shared__ __align__(16) char dyn[];
    __shared__ unsigned char mR8[36], mC8[36], mR4[10], mC4[10];

    const int tid  = threadIdx.x;
    const int team = tid >> 8, rt = tid & 255;
    const int b    = blockIdx.x * 2 + team;
    const int bar  = 1 + team;
    FwdS& s = ((FwdS*)dyn)[team];
    const int mm = team ? (rt ^ 64) : rt;      // SMSP-disjoint role index

    if (tid == 0) {
        int e = 0;
        for (int r = 0; r < 8; ++r)
            for (int c = r; c < 8; ++c) { mR8[e] = (unsigned char)r; mC8[e] = (unsigned char)c; ++e; }
        e = 0;
        for (int r = 0; r < 4; ++r)
            for (int c = r; c < 4; ++c) { mR4[e] = (unsigned char)r; mC4[e] = (unsigned char)c; ++e; }
    }
    {
        const size_t o = (size_t)b * T;
        const float* A0 = A  + o * NS * NS;
        const float* C0 = C  + o * PD * NS;
        const float* B0 = Bm + o * NS * MD;
        for (int e = rt; e < NS * NS; e += 256) {
            float v = A0[e];
            s.At[e & 31][e >> 5] = v; s.An[e >> 5][e & 31] = v;
            s.Sig[e >> 5][e & 31] = Sig0[e];
        }
        for (int e = rt; e < PD * NS; e += 256) s.Ct[e & 31][e >> 5] = C0[e];
        s.B[rt >> 3][rt & 7] = B0[rt];
        if (rt < PD) s.y[rt] = Y[o * PD + rt];
        else if (rt < PD + MD) s.uu[rt - PD] = U[o * MD + (rt - PD)];
        if (rt >= 32 && rt < 64) s.mu[rt - 32] = mu0[rt - 32];
    }
    __syncthreads();

    for (int t = 0; t < T; ++t) {
        const size_t bt = (size_t)b * T + t;

        // --- P1: T1 (both layouts, 64 tiles) ; mu_p [64,96) ; G=C*A [96,128) ; CC=C*C^T [128,138) ---
        if (mm < 64) {
            const int i0 = 4 * (mm >> 3), j0 = 4 * (mm & 7);
            float c[4][4] = {};
            #pragma unroll 8
            for (int k = 0; k < NS; ++k) {
                float4 a  = *(const float4*)&s.At[k][i0];
                float4 bb = *(const float4*)&s.Sig[k][j0];
                c[0][0] += a.x * bb.x; c[0][1] += a.x * bb.y; c[0][2] += a.x * bb.z; c[0][3] += a.x * bb.w;
                c[1][0] += a.y * bb.x; c[1][1] += a.y * bb.y; c[1][2] += a.y * bb.z; c[1][3] += a.y * bb.w;
                c[2][0] += a.z * bb.x; c[2][1] += a.z * bb.y; c[2][2] += a.z * bb.z; c[2][3] += a.z * bb.w;
                c[3][0] += a.w * bb.x; c[3][1] += a.w * bb.y; c[3][2] += a.w * bb.z; c[3][3] += a.w * bb.w;
            }
            #pragma unroll
            for (int m = 0; m < 4; ++m) {
                #pragma unroll
                for (int n = 0; n < 4; ++n) s.T1t[j0 + n][i0 + m] = c[m][n];
                *(float4*)&s.T1n[i0 + m][j0] = make_float4(c[m][0], c[m][1], c[m][2], c[m][3]);
            }
        } else if (mm < 96) {
            const int i = mm - 64;
            float acc = 0.f;
            #pragma unroll 8
            for (int k = 0; k < NS; ++k) acc += s.At[k][i] * s.mu[k];
            #pragma unroll
            for (int k = 0; k < MD; ++k) acc += s.B[i][k] * s.uu[k];
            s.mup[i] = acc;
        } else if (mm < 128) {
            const int g = mm - 96;                      // G: 16x32 -> 4x8 grid of 4x4
            const int c0 = 4 * (g >> 3), j0 = 4 * (g & 7);
            float c[4][4] = {};
            #pragma unroll 8
            for (int k = 0; k < NS; ++k) {
                float4 a  = *(const float4*)&s.Ct[k][c0];
                float4 bb = *(const float4*)&s.An[k][j0];
                c[0][0] += a.x * bb.x; c[0][1] += a.x * bb.y; c[0][2] += a.x * bb.z; c[0][3] += a.x * bb.w;
                c[1][0] += a.y * bb.x; c[1][1] += a.y * bb.y; c[1][2] += a.y * bb.z; c[1][3] += a.y * bb.w;
                c[2][0] += a.z * bb.x; c[2][1] += a.z * bb.y; c[2][2] += a.z * bb.z; c[2][3] += a.z * bb.w;
                c[3][0] += a.w * bb.x; c[3][1] += a.w * bb.y; c[3][2] += a.w * bb.z; c[3][3] += a.w * bb.w;
            }
            #pragma unroll
            for (int m = 0; m < 4; ++m)
                #pragma unroll
                for (int n = 0; n < 4; ++n) s.Gt[j0 + n][c0 + m] = c[m][n];
        } else if (mm < 138) {
            const int ti = mR4[mm - 128], tj = mC4[mm - 128];   // CC: 16x16 sym
            const int i0 = 4 * ti, j0 = 4 * tj;
            float c[4][4] = {};
            #pragma unroll 8
            for (int k = 0; k < NS; ++k) {
                float4 a  = *(const float4*)&s.Ct[k][i0];
                float4 bb = *(const float4*)&s.Ct[k][j0];
                c[0][0] += a.x * bb.x; c[0][1] += a.x * bb.y; c[0][2] += a.x * bb.z; c[0][3] += a.x * bb.w;
                c[1][0] += a.y * bb.x; c[1][1] += a.y * bb.y; c[1][2] += a.y * bb.z; c[1][3] += a.y * bb.w;
                c[2][0] += a.z * bb.x; c[2][1] += a.z * bb.y; c[2][2] += a.z * bb.z; c[2][3] += a.z * bb.w;
                c[3][0] += a.w * bb.x; c[3][1] += a.w * bb.y; c[3][2] += a.w * bb.z; c[3][3] += a.w * bb.w;
            }
            #pragma unroll
            for (int m = 0; m < 4; ++m)
                #pragma unroll
                for (int n = 0; n < 4; ++n) {
                    s.CC[i0 + m][j0 + n] = c[m][n];
                    if (ti != tj) s.CC[j0 + n][i0 + m] = c[m][n];
                }
        }
        TBAR(bar);

        // --- P2: Sp(36 sym tiles) ; r [36,52) ; W=T1*G^T+qC^T [64,96) ; H=C*T1 [96,128) ; g_mup [128,160) ---
        if (mm < 36) {
            const int ti = mR8[mm], tj = mC8[mm];
            const int i0 = 4 * ti, j0 = 4 * tj;
            float c[4][4] = {};
            #pragma unroll 8
            for (int k = 0; k < NS; ++k) {
                float4 a  = *(const float4*)&s.T1t[k][i0];
                float4 bb = *(const float4*)&s.At[k][j0];
                c[0][0] += a.x * bb.x; c[0][1] += a.x * bb.y; c[0][2] += a.x * bb.z; c[0][3] += a.x * bb.w;
                c[1][0] += a.y * bb.x; c[1][1] += a.y * bb.y; c[1][2] += a.y * bb.z; c[1][3] += a.y * bb.w;
                c[2][0] += a.z * bb.x; c[2][1] += a.z * bb.y; c[2][2] += a.z * bb.z; c[2][3] += a.z * bb.w;
                c[3][0] += a.w * bb.x; c[3][1] += a.w * bb.y; c[3][2] += a.w * bb.z; c[3][3] += a.w * bb.w;
            }
            if (ti == tj) {
                #pragma unroll
                for (int m = 0; m < 4; ++m) {
                    c[m][m] += QVAR;
                    #pragma unroll
                    for (int n = m + 1; n < 4; ++n) { float av = 0.5f * (c[m][n] + c[n][m]); c[m][n] = av; c[n][m] = av; }
                }
            }
            #pragma unroll
            for (int m = 0; m < 4; ++m)
                #pragma unroll
                for (int n = 0; n < 4; ++n) {
                    s.Sp[i0 + m][j0 + n] = c[m][n];
                    if (ti != tj) s.Sp[j0 + n][i0 + m] = c[m][n];
                }
        } else if (mm < 52) {
            const int i = mm - 36;
            float acc = s.y[i];
            #pragma unroll 8
            for (int k = 0; k < NS; ++k) acc -= s.Ct[k][i] * s.mup[k];
            s.r[i] = acc;
        } else if (mm >= 64 && mm < 96) {
            const int w = mm - 64;                      // W: 32x16 -> 8x4 grid
            const int i0 = 4 * (w >> 2), c0 = 4 * (w & 3);
            float c[4][4];
            #pragma unroll
            for (int m = 0; m < 4; ++m) {
                float4 cv = *(const float4*)&s.Ct[i0 + m][c0];
                c[m][0] = QVAR * cv.x; c[m][1] = QVAR * cv.y; c[m][2] = QVAR * cv.z; c[m][3] = QVAR * cv.w;
            }
            #pragma unroll 8
            for (int k = 0; k < NS; ++k) {
                float4 a  = *(const float4*)&s.T1t[k][i0];
                float4 bb = *(const float4*)&s.Gt[k][c0];
                c[0][0] += a.x * bb.x; c[0][1] += a.x * bb.y; c[0][2] += a.x * bb.z; c[0][3] += a.x * bb.w;
                c[1][0] += a.y * bb.x; c[1][1] += a.y * bb.y; c[1][2] += a.y * bb.z; c[1][3] += a.y * bb.w;
                c[2][0] += a.z * bb.x; c[2][1] += a.z * bb.y; c[2][2] += a.z * bb.z; c[2][3] += a.z * bb.w;
                c[3][0] += a.w * bb.x; c[3][1] += a.w * bb.y; c[3][2] += a.w * bb.z; c[3][3] += a.w * bb.w;
            }
            #pragma unroll
            for (int m = 0; m < 4; ++m) {
                *(float4*)&s.W[i0 + m][c0] = make_float4(c[m][0], c[m][1], c[m][2], c[m][3]);
                #pragma unroll
                for (int n = 0; n < 4; ++n) s.Wt[c0 + n][i0 + m] = c[m][n];
            }
        } else if (mm >= 96 && mm < 128) {
            const int h = mm - 96;                      // H: 16x32 -> 4x8 grid
            const int c0 = 4 * (h >> 3), j0 = 4 * (h & 7);
            float c[4][4] = {};
            #pragma unroll 8
            for (int k = 0; k < NS; ++k) {
                float4 a  = *(const float4*)&s.Ct[k][c0];
                float4 bb = *(const float4*)&s.T1n[k][j0];
                c[0][0] += a.x * bb.x; c[0][1] += a.x * bb.y; c[0][2] += a.x * bb.z; c[0][3] += a.x * bb.w;
                c[1][0] += a.y * bb.x; c[1][1] += a.y * bb.y; c[1][2] += a.y * bb.z; c[1][3] += a.y * bb.w;
                c[2][0] += a.z * bb.x; c[2][1] += a.z * bb.y; c[2][2] += a.z * bb.z; c[2][3] += a.z * bb.w;
                c[3][0] += a.w * bb.x; c[3][1] += a.w * bb.y; c[3][2] += a.w * bb.z; c[3][3] += a.w * bb.w;
            }
            #pragma unroll
            for (int m = 0; m < 4; ++m)
                #pragma unroll
                for (int n = 0; n < 4; ++n) s.Ht[j0 + n][c0 + m] = c[m][n];
        } else if (mm >= 128 && mm < 160) {
            g_mup[bt * NS + (mm - 128)] = s.mup[mm - 128];
        }
        TBAR(bar);

        // --- P3: S = sym(H*G^T + q*CC) + R (10 tiles) ; g_Sigp store [128,256) ---
        if (mm < 10) {
            const int ti = mR4[mm], tj = mC4[mm];
            const int i0 = 4 * ti, j0 = 4 * tj;
            float c[4][4];
            #pragma unroll
            for (int m = 0; m < 4; ++m) {
                float4 cc = *(const float4*)&s.CC[i0 + m][j0];
                c[m][0] = QVAR * cc.x; c[m][1] = QVAR * cc.y; c[m][2] = QVAR * cc.z; c[m][3] = QVAR * cc.w;
            }
            #pragma unroll 8
            for (int k = 0; k < NS; ++k) {
                float4 a  = *(const float4*)&s.Ht[k][i0];
                float4 bb = *(const float4*)&s.Gt[k][j0];
                c[0][0] += a.x * bb.x; c[0][1] += a.x * bb.y; c[0][2] += a.x * bb.z; c[0][3] += a.x * bb.w;
                c[1][0] += a.y * bb.x; c[1][1] += a.y * bb.y; c[1][2] += a.y * bb.z; c[1][3] += a.y * bb.w;
                c[2][0] += a.z * bb.x; c[2][1] += a.z * bb.y; c[2][2] += a.z * bb.z; c[2][3] += a.z * bb.w;
                c[3][0] += a.w * bb.x; c[3][1] += a.w * bb.y; c[3][2] += a.w * bb.z; c[3][3] += a.w * bb.w;
            }
            if (ti == tj) {
                #pragma unroll
                for (int m = 0; m < 4; ++m) {
                    c[m][m] += RVAR;
                    #pragma unroll
                    for (int n = m + 1; n < 4; ++n) { float av = 0.5f * (c[m][n] + c[n][m]); c[m][n] = av; c[n][m] = av; }
                }
            }
            #pragma unroll
            for (int m = 0; m < 4; ++m)
                #pragma unroll
                for (int n = 0; n < 4; ++n) {
                    s.S[i0 + m][j0 + n] = c[m][n];
                    if (ti != tj) s.S[j0 + n][i0 + m] = c[m][n];
                }
        } else if (mm >= 128) {
            float* gp = g_Sigp + bt * NS * NS;
            for (int e = mm - 128; e < NS * NS; e += 128) gp[e] = s.Sp[e >> 5][e & 31];
        }
        TBAR(bar);

        // --- P4: chol16+solve -> Kt (warp mm<32) ; others prefetch t+1 ---
        if (mm < 32) {
            const int i = rt & 31;
            float dinv[PD];
            #pragma unroll
            for (int k = 0; k < PD; ++k) {
                float dkk = s.S[k][k];
                float rs  = rsqrtf(dkk);
                dinv[k] = rs;
                __syncwarp();
                if (i == k) s.S[k][k] = dkk * rs;
                if (i > k && i < PD) s.S[i][k] *= rs;
                __syncwarp();
                if (i > k && i < PD) {
                    float lik = s.S[i][k];
                    for (int j2 = k + 1; j2 <= i; ++j2) s.S[i][j2] -= lik * s.S[j2][k];
                }
                __syncwarp();
            }
            {
                float x[PD];
                #pragma unroll
                for (int r2 = 0; r2 < PD; ++r2) {
                    float a0 = s.W[i][r2], a1 = 0.f;
                    #pragma unroll
                    for (int k = 0; k < r2; ++k) {
                        if (k & 1) a1 += s.S[r2][k] * x[k];
                        else       a0 -= s.S[r2][k] * x[k];
                    }
                    x[r2] = (a0 - a1) * dinv[r2];
                }
                #pragma unroll
                for (int r2 = PD - 1; r2 >= 0; --r2) {
                    float a0 = x[r2], a1 = 0.f;
                    #pragma unroll
                    for (int k = r2 + 1; k < PD; ++k) {
                        if (k & 1) a1 += s.S[k][r2] * x[k];
                        else       a0 -= s.S[k][r2] * x[k];
                    }
                    x[r2] = (a0 - a1) * dinv[r2];
                }
                #pragma unroll
                for (int r2 = 0; r2 < PD; ++r2) s.Kt[r2][i] = x[r2];
            }
        } else if (t + 1 < T) {
            const size_t bt1 = bt + 1;
            const float* An = A  + bt1 * NS * NS;
            const float* Cn = C  + bt1 * PD * NS;
            const float* Bn = Bm + bt1 * NS * MD;
            const int q = mm - 32;
            for (int e = q; e < NS * NS; e += 224) {
                float v = An[e];
                s.At[e & 31][e >> 5] = v; s.An[e >> 5][e & 31] = v;
            }
            for (int e = q; e < PD * NS; e += 224) s.Ct[e & 31][e >> 5] = Cn[e];
            for (int e = q; e < NS * MD; e += 224) s.B[e >> 3][e & 7] = Bn[e];
            if (q < PD) s.y[q] = Y[bt1 * PD + q];
            else if (q < PD + MD) s.uu[q - PD] = U[bt1 * MD + (q - PD)];
        }
        TBAR(bar);

        // --- P5: Sigf = sym(Sp - K W^T) (36 tiles) ; mu_f [64,96) ---
        {
            float* gf = g_Sigf + bt * NS * NS;
            float* ob = out + bt * (size_t)(NS * (NS + 1));
            if (mm < 36) {
                const int ti = mR8[mm], tj = mC8[mm];
                const int i0 = 4 * ti, j0 = 4 * tj;
                float c[4][4];
                #pragma unroll
                for (int m = 0; m < 4; ++m) {
                    float4 sp = *(const float4*)&s.Sp[i0 + m][j0];
                    c[m][0] = sp.x; c[m][1] = sp.y; c[m][2] = sp.z; c[m][3] = sp.w;
                }
                #pragma unroll
                for (int k = 0; k < PD; ++k) {
                    float4 a  = *(const float4*)&s.Kt[k][i0];
                    float4 bb = *(const float4*)&s.Wt[k][j0];
                    c[0][0] -= a.x * bb.x; c[0][1] -= a.x * bb.y; c[0][2] -= a.x * bb.z; c[0][3] -= a.x * bb.w;
                    c[1][0] -= a.y * bb.x; c[1][1] -= a.y * bb.y; c[1][2] -= a.y * bb.z; c[1][3] -= a.y * bb.w;
                    c[2][0] -= a.z * bb.x; c[2][1] -= a.z * bb.y; c[2][2] -= a.z * bb.z; c[2][3] -= a.z * bb.w;
                    c[3][0] -= a.w * bb.x; c[3][1] -= a.w * bb.y; c[3][2] -= a.w * bb.z; c[3][3] -= a.w * bb.w;
                }
                if (ti == tj) {
                    #pragma unroll
                    for (int m = 0; m < 4; ++m)
                        #pragma unroll
                        for (int n = m + 1; n < 4; ++n) { float av = 0.5f * (c[m][n] + c[n][m]); c[m][n] = av; c[n][m] = av; }
                }
                #pragma unroll
                for (int m = 0; m < 4; ++m)
                    #pragma unroll
                    for (int n = 0; n < 4; ++n) {
                        s.Sig[i0 + m][j0 + n] = c[m][n];
                        gf[(i0 + m) * NS + j0 + n] = c[m][n];
                        if (t == T - 1) ob[(i0 + m) * (NS + 1) + 1 + j0 + n] = c[m][n];
                        if (ti != tj) {
                            s.Sig[j0 + n][i0 + m] = c[m][n];
                            gf[(j0 + n) * NS + i0 + m] = c[m][n];
                            if (t == T - 1) ob[(j0 + n) * (NS + 1) + 1 + i0 + m] = c[m][n];
                        }
                    }
            } else if (mm >= 64 && mm < 96) {
                const int i = mm - 64;
                float acc = s.mup[i];
                #pragma unroll
                for (int k = 0; k < PD; ++k) acc += s.Kt[k][i] * s.r[k];
                s.mu[i] = acc;
                g_muf[bt * NS + i] = acc;
                if (t == T - 1) ob[i * (NS + 1)] = acc;
            }
        }
        TBAR(bar);
    }
}

// ============================ J PRECOMPUTE (fully parallel) ============================
__global__ __launch_bounds__(32, 1)
void jpre_kernel(const float* __restrict__ A)
{
    __shared__ __align__(16) float sl[NS][33];
    const int lane = threadIdx.x;
    const int b = blockIdx.x;
    const int t = blockIdx.y;
    const size_t bt = (size_t)b * T + t;
    const float* Ag  = A      + bt * NS * NS;
    const float* Sfg = g_Sigf + bt * NS * NS;
    const float* Spg = g_Sigp + (bt + 1) * NS * NS;

    #pragma unroll
    for (int e = lane; e < NS * NS / 4; e += 32) {
        float4 v = ((const float4*)Ag)[e];
        int r = (4 * e) >> 5, c = (4 * e) & 31;
        sl[r][c] = v.x; sl[r][c + 1] = v.y; sl[r][c + 2] = v.z; sl[r][c + 3] = v.w;
    }
    float sf[NS];
    #pragma unroll
    for (int q = 0; q < 8; ++q) {
        float4 v = ((const float4*)(Sfg + lane * NS))[q];
        sf[4 * q] = v.x; sf[4 * q + 1] = v.y; sf[4 * q + 2] = v.z; sf[4 * q + 3] = v.w;
    }
    __syncwarp();
    float m[NS];
    #pragma unroll
    for (int r = 0; r < NS; ++r) {
        float a0 = 0.f, a1 = 0.f;
        #pragma unroll 8
        for (int k = 0; k < NS; k += 2) { a0 += sf[k] * sl[r][k]; a1 += sf[k + 1] * sl[r][k + 1]; }
        m[r] = a0 + a1;
    }
    __syncwarp();
    #pragma unroll
    for (int e = lane; e < NS * NS / 4; e += 32) {
        float4 v = ((const float4*)Spg)[e];
        int r = (4 * e) >> 5, c = (4 * e) & 31;
        sl[r][c] = v.x; sl[r][c + 1] = v.y; sl[r][c + 2] = v.z; sl[r][c + 3] = v.w;
    }
    __syncwarp();
    {
        const int i = lane;
        #pragma unroll 1
        for (int k = 0; k < NS; ++k) {
            float dkk = sl[k][k];
            float rs  = rsqrtf(dkk);
            __syncwarp();
            if (i == k) { sl[k][k] = dkk * rs; sl[k][32] = rs; }
            if (i > k) sl[i][k] *= rs;
            __syncwarp();
            if (i > k) {
                float lik = sl[i][k];
                for (int j2 = k + 1; j2 <= i; ++j2) sl[i][j2] -= lik * sl[j2][k];
            }
            __syncwarp();
        }
    }
    float x[NS];
    #pragma unroll
    for (int r = 0; r < NS; ++r) {
        float a0 = m[r], a1 = 0.f;
        #pragma unroll
        for (int k = 0; k < r; ++k) {
            if (k & 1) a1 += sl[r][k] * x[k];
            else       a0 -= sl[r][k] * x[k];
        }
        x[r] = (a0 - a1) * sl[r][32];
    }
    #pragma unroll
    for (int r = NS - 1; r >= 0; --r) {
        float a0 = x[r], a1 = 0.f;
        #pragma unroll
        for (int k = r + 1; k < NS; ++k) {
            if (k & 1) a1 += sl[k][r] * x[k];
            else       a0 -= sl[k][r] * x[k];
        }
        x[r] = (a0 - a1) * sl[r][32];
    }
    float* Jg = g_J + bt * NS * NS;
    #pragma unroll
    for (int k = 0; k < NS; ++k) Jg[k * NS + lane] = x[k];
}

// ============================ BACKWARD SMOOTHER (2 teams / CTA, 2x2 tiles — R9 form) ============================
__global__ __launch_bounds__(512, 1)
void bwd_kernel(float* __restrict__ out)
{
    extern __shared__ __align__(16) char dyn[];
    __shared__ unsigned char mapR[136], mapC[136];

    const int tid  = threadIdx.x;
    const int team = tid >> 8, rt = tid & 255;
    const int b    = blockIdx.x * 2 + team;
    const int bar  = 1 + team;
    BwdS& s = ((BwdS*)dyn)[team];
    const int tr = rt >> 4, tc = rt & 15;

    if (tid == 0) {
        int e = 0;
        for (int r = 0; r < 16; ++r)
            for (int c = r; c < 16; ++c) { mapR[e] = (unsigned char)r; mapC[e] = (unsigned char)c; ++e; }
    }
    {
        const int t0 = T - 2, p0 = t0 & 1;
        const size_t bt  = (size_t)b * T + t0;
        const size_t btL = (size_t)b * T + (T - 1);
        const float* Sfg = g_Sigf + bt * NS * NS;
        const float* Spg = g_Sigp + (bt + 1) * NS * NS;
        const float* Jg  = g_J    + bt * NS * NS;
        const float* SfL = g_Sigf + btL * NS * NS;
        for (int e = rt; e < NS * NS; e += 256) {
            s.Sf[p0][e >> 5][e & 31] = Sfg[e];
            s.Sp[p0][e >> 5][e & 31] = Spg[e];
            s.Jt[p0][e >> 5][e & 31] = Jg[e];
            s.Sig[e >> 5][e & 31]    = SfL[e];
        }
        if (rt < NS) { s.mufB[p0][rt] = g_muf[bt * NS + rt]; s.muP[(T - 1) & 1][rt] = g_muf[btL * NS + rt]; }
        else if (rt < 2 * NS) s.mupB[p0][rt - NS] = g_mup[(bt + 1) * NS + (rt - NS)];
    }
    __syncthreads();

    for (int t = T - 2; t >= 0; --t) {
        const size_t bt = (size_t)b * T + t;
        const int p = t & 1;
        float (*Jt)[ST] = s.Jt[p];
        float (*Sf)[ST] = s.Sf[p];
        float (*Sp)[ST] = s.Sp[p];
        float* ob = out + bt * (size_t)(NS * (NS + 1));

        // phaseA: T1^T = (J (Sig_s - Sp))^T  (256 2x2 tiles)
        {
            const int i0 = 2 * tr, j0 = 2 * tc;
            float c00 = 0.f, c01 = 0.f, c10 = 0.f, c11 = 0.f;
            #pragma unroll 8
            for (int k = 0; k < NS; ++k) {
                float2 a  = *(const float2*)&Jt[k][i0];
                float2 s1 = *(const float2*)&s.Sig[k][j0];
                float2 s2 = *(const float2*)&Sp[k][j0];
                float bx = s1.x - s2.x, by = s1.y - s2.y;
                c00 += a.x * bx; c01 += a.x * by; c10 += a.y * bx; c11 += a.y * by;
            }
            s.T1[j0][i0] = c00; s.T1[j0 + 1][i0] = c01; s.T1[j0][i0 + 1] = c10; s.T1[j0 + 1][i0 + 1] = c11;
        }
        TBAR(bar);

        // phaseB: Sig_n = sym(Sf + T1 J^T) [136] ; mu_n [32] ; prefetch t-1 [88]
        if (rt < 136) {
            const int i0 = 2 * mapR[rt], j0 = 2 * mapC[rt];
            float c00 = Sf[i0][j0],     c01 = Sf[i0][j0 + 1];
            float c10 = Sf[i0 + 1][j0], c11 = Sf[i0 + 1][j0 + 1];
            #pragma unroll 8
            for (int k = 0; k < NS; ++k) {
                float2 a  = *(const float2*)&s.T1[k][i0];
                float2 bb = *(const float2*)&Jt[k][j0];
                c00 += a.x * bb.x; c01 += a.x * bb.y; c10 += a.y * bb.x; c11 += a.y * bb.y;
            }
            if (i0 == j0) { float av = 0.5f * (c01 + c10); c01 = av; c10 = av; }
            s.Sig[i0][j0] = c00; s.Sig[i0][j0 + 1] = c01; s.Sig[i0 + 1][j0] = c10; s.Sig[i0 + 1][j0 + 1] = c11;
            ob[i0 * (NS + 1) + 1 + j0] = c00; ob[i0 * (NS + 1) + 2 + j0] = c01;
            ob[(i0 + 1) * (NS + 1) + 1 + j0] = c10; ob[(i0 + 1) * (NS + 1) + 2 + j0] = c11;
            if (i0 != j0) {
                s.Sig[j0][i0] = c00; s.Sig[j0 + 1][i0] = c01; s.Sig[j0][i0 + 1] = c10; s.Sig[j0 + 1][i0 + 1] = c11;
                ob[j0 * (NS + 1) + 1 + i0] = c00; ob[(j0 + 1) * (NS + 1) + 1 + i0] = c01;
                ob[j0 * (NS + 1) + 2 + i0] = c10; ob[(j0 + 1) * (NS + 1) + 2 + i0] = c11;
            }
        } else if (rt < 168) {
            const int i = rt - 136;
            float acc = s.mufB[p][i];
            #pragma unroll 8
            for (int k = 0; k < NS; ++k) acc += Jt[k][i] * (s.muP[p ^ 1][k] - s.mupB[p][k]);
            s.muP[p][i] = acc;
            ob[i * (NS + 1)] = acc;
        } else if (t > 0) {
            const int q = rt - 168;
            const size_t btm = bt - 1;
            const float* Sfg = g_Sigf + btm * NS * NS;
            const float* Spg = g_Sigp + bt * NS * NS;
            const float* Jg  = g_J    + btm * NS * NS;
            const int pn = p ^ 1;
            for (int e = q; e < NS * NS; e += 88) {
                s.Sf[pn][e >> 5][e & 31] = Sfg[e];
                s.Sp[pn][e >> 5][e & 31] = Spg[e];
                s.Jt[pn][e >> 5][e & 31] = Jg[e];
            }
            if (q < NS) s.mufB[pn][q] = g_muf[btm * NS + q];
            else if (q < 2 * NS) s.mupB[pn][q - NS] = g_mup[bt * NS + (q - NS)];
        }
        TBAR(bar);
    }
}

extern "C" void kernel_launch(void* const* d_in, const int* in_sizes, int n_in,
                              void* d_out, int out_size)
{
    const float* Y    = (const float*)d_in[0];
    const float* U    = (const float*)d_in[1];
    const float* A    = (const float*)d_in[2];
    const float* Bm   = (const float*)d_in[3];
    const float* C    = (const float*)d_in[4];
    const float* mu0  = (const float*)d_in[5];
    const float* Sig0 = (const float*)d_in[6];
    float* out = (float*)d_out;

    cudaFuncSetAttribute(fwd_kernel, cudaFuncAttributeMaxDynamicSharedMemorySize,
                         (int)(2 * sizeof(FwdS)));
    cudaFuncSetAttribute(bwd_kernel, cudaFuncAttributeMaxDynamicSharedMemorySize,
                         (int)(2 * sizeof(BwdS)));

    fwd_kernel<<<BATCH / 2, 512, 2 * sizeof(FwdS)>>>(Y, U, A, Bm, C, mu0, Sig0, out);
    jpre_kernel<<<dim3(BATCH, T - 1), 32>>>(A);
    bwd_kernel<<<BATCH / 2, 512, 2 * sizeof(BwdS)>>>(out);
}